// round 6
// baseline (speedup 1.0000x reference)
#include <cuda_runtime.h>
#include <cuda_bf16.h>

// Involution: B=4, C=256, G=16, K=7, S=1, P=3, H=W=56
#define HW 3136
#define XCH 634    // xt per-channel stride (= 2*317, 317 odd -> odd bankpair spread)
#define WSTR 66    // padded span_w row stride (7*66 % 32 = 14 -> kk bank spread)
#define KSTR 228   // kern row stride (mult of 4 for STS.128; 228 % 32 = 4)

__device__ float g_h[4 * 64 * HW];   // h = reduce(x): (4,64,3136) fp32

// ---- f32x2 helpers ----
union F2 { float2 f; unsigned long long u; };
union F4 { float4 f; unsigned long long u[2]; };
__device__ __forceinline__ unsigned long long pk2f(float lo, float hi) {
    unsigned long long d;
    asm("mov.b64 %0, {%1, %2};" : "=l"(d) : "f"(lo), "f"(hi));
    return d;
}
__device__ __forceinline__ void unpk2(unsigned long long v, float& lo, float& hi) {
    asm("mov.b64 {%0, %1}, %2;" : "=f"(lo), "=f"(hi) : "l"(v));
}
__device__ __forceinline__ unsigned long long ffma2(
    unsigned long long a, unsigned long long b, unsigned long long c) {
    unsigned long long d;
    asm("fma.rn.f32x2 %0, %1, %2, %3;" : "=l"(d) : "l"(a), "l"(b), "l"(c));
    return d;
}
__device__ __forceinline__ unsigned long long add2(
    unsigned long long a, unsigned long long b) {
    unsigned long long d;
    asm("add.rn.f32x2 %0, %1, %2;" : "=l"(d) : "l"(a), "l"(b));
    return d;
}

// ---------------------------------------------------------------------------
// Kernel 1: h[b,o,p] = sum_c x[b,c,p]*rw[o,c] + rb[o]   (unchanged from R5)
// ---------------------------------------------------------------------------
__global__ __launch_bounds__(256) void reduce_kernel(
    const float* __restrict__ x,
    const float* __restrict__ rw,
    const float* __restrict__ rb)
{
    const int b  = blockIdx.y;
    const int n0 = blockIdx.x * 112;
    __shared__ float ws[64 * 32];
    __shared__ float xs[32 * 112];

    const int tid = threadIdx.x;
    const int og = tid / 14;
    const int pg = tid % 14;
    const int o0 = og * 4;
    const bool act = (tid < 224);

    unsigned long long acc[4][4];
    #pragma unroll
    for (int i = 0; i < 4; i++)
        #pragma unroll
        for (int m = 0; m < 4; m++) acc[i][m] = 0ull;

    for (int kb = 0; kb < 256; kb += 32) {
        #pragma unroll
        for (int i = 0; i < 8; i++) {
            int e = tid + i * 256;
            ws[e] = rw[(e >> 5) * 256 + kb + (e & 31)];
        }
        #pragma unroll
        for (int i = 0; i < 14; i++) {
            int e = tid + i * 256;
            int k = e / 112, p = e - k * 112;
            xs[e] = x[(b * 256 + kb + k) * HW + n0 + p];
        }
        __syncthreads();

        if (act) {
            #pragma unroll 2
            for (int k2 = 0; k2 < 16; k2++) {
                unsigned long long w2[4], h0[4], h1[4];
                #pragma unroll
                for (int i = 0; i < 4; i++) {
                    F2 t; t.f = *(const float2*)&ws[(o0 + i) * 32 + 2 * k2];
                    w2[i] = t.u;
                }
                #pragma unroll
                for (int m = 0; m < 4; m++) {
                    F2 t; t.f = *(const float2*)&xs[(2 * k2) * 112 + 2 * pg + 28 * m];
                    h0[m] = t.u;
                }
                #pragma unroll
                for (int m = 0; m < 4; m++) {
                    F2 t; t.f = *(const float2*)&xs[(2 * k2 + 1) * 112 + 2 * pg + 28 * m];
                    h1[m] = t.u;
                }
                #pragma unroll
                for (int i = 0; i < 4; i++) {
                    float wl, wh;
                    unpk2(w2[i], wl, wh);
                    unsigned long long wll = pk2f(wl, wl);
                    unsigned long long whh = pk2f(wh, wh);
                    #pragma unroll
                    for (int m = 0; m < 4; m++) acc[i][m] = ffma2(wll, h0[m], acc[i][m]);
                    #pragma unroll
                    for (int m = 0; m < 4; m++) acc[i][m] = ffma2(whh, h1[m], acc[i][m]);
                }
            }
        }
        __syncthreads();
    }

    if (act) {
        #pragma unroll
        for (int i = 0; i < 4; i++) {
            float bias = rb[o0 + i];
            unsigned long long bd = pk2f(bias, bias);
            #pragma unroll
            for (int m = 0; m < 4; m++) {
                F2 r; r.u = add2(acc[i][m], bd);
                *(float2*)&g_h[(b * 64 + o0 + i) * HW + n0 + 2 * pg + 28 * m] = r.f;
            }
        }
    }
}

// ---------------------------------------------------------------------------
// Kernel 2 (fused span GEMM + apply). grid (14,16,4), block 256, 2 CTAs/SM.
// Phase 1: warp w owns pairs 16w..16w+15; lane=(kkg=lane/4, pl=lane&3).
//          All 49 kk live in one warp -> h read ONCE (LDS.128, 1 wf);
//          w rows padded to WSTR=66 -> 7 distinct bankpairs (1 wf).
// Phase 2: thread = 4 px (pd=tid>>2) x 4 interleaved channels (ch=cq+4i,
//          cq=tid&3). Odd per-cq bankpair shift (317*cq) keeps every x
//          LDS.64 at the dense 2-wf floor. kern at stride KSTR=228.
// ---------------------------------------------------------------------------
__global__ __launch_bounds__(256, 2) void inv_kernel(
    const float* __restrict__ x,
    const float* __restrict__ sw,
    const float* __restrict__ sb,
    float* __restrict__ out)
{
    const int r0 = blockIdx.x * 4;
    const int g  = blockIdx.y;
    const int b  = blockIdx.z;

    extern __shared__ float smem[];
    float* wsp   = smem;              // 3240 (49 x WSTR used)
    float* sbias = smem + 3240;       // 72
    float* hsk   = smem + 3312;       // 14336 : h[64][224], later kern[49][KSTR]
    float* xt    = hsk + 14336;       // 16*634 : x halo 16ch x (10r x 62c)

    const int tid = threadIdx.x;

    // ---- stage span_w into padded rows ----
    {
        const float2* swv = (const float2*)(sw + g * 3136);
        #pragma unroll
        for (int i = 0; i < 7; i++) {
            int e = tid + i * 256;
            if (e < 1568) {
                int kk = e >> 5, c2 = e & 31;
                *(float2*)&wsp[kk * WSTR + 2 * c2] = swv[e];
            }
        }
    }
    if (tid < 49) sbias[tid] = sb[g * 49 + tid];

    // ---- stage h tile ----
    {
        float4* hsv = (float4*)hsk;
        #pragma unroll
        for (int i = 0; i < 14; i++) {
            int e = tid + i * 256;
            int c = e / 56, p4 = e - c * 56;
            hsv[e] = *(const float4*)&g_h[(b * 64 + c) * HW + r0 * 56 + p4 * 4];
        }
    }

    // ---- stage x halo tile ----
    #pragma unroll
    for (int i = 0; i < 39; i++) {
        int e = tid + i * 256;
        if (e < 16 * 620) {
            int cg  = e / 620;
            int rem = e - cg * 620;
            int rr  = rem / 62, cc = rem - rr * 62;
            int gr = r0 + rr - 3;
            int gc = cc - 3;
            float v = 0.f;
            if (gr >= 0 && gr < 56 && gc >= 0 && gc < 56)
                v = x[(b * 256 + g * 16 + cg) * HW + gr * 56 + gc];
            xt[cg * XCH + rem] = v;
        }
    }
    __syncthreads();

    // ---- Phase 1: kern = ws @ hs ----
    const int lane = tid & 31, wrp = tid >> 5;
    const int kkg = lane >> 2, pl = lane & 3;      // kkg 0..7 (7 idle), pl 0..3
    const bool p1act = (lane < 28) && (wrp < 7);
    const int pb = 16 * wrp + 4 * pl;              // first of this thread's 4 pairs

    unsigned long long kacc[7][4];
    #pragma unroll
    for (int i = 0; i < 7; i++)
        #pragma unroll
        for (int j = 0; j < 4; j++) kacc[i][j] = 0ull;

    if (p1act) {
        const float* wbase = wsp + kkg * 7 * WSTR;
        #pragma unroll 1
        for (int c2 = 0; c2 < 32; c2++) {
            unsigned long long w2[7];
            #pragma unroll
            for (int i = 0; i < 7; i++) {
                F2 t; t.f = *(const float2*)&wbase[i * WSTR + 2 * c2];
                w2[i] = t.u;
            }
            F4 a0, a1, b0, b1;
            a0.f = *(const float4*)&hsk[(2 * c2) * 224 + 2 * pb];
            a1.f = *(const float4*)&hsk[(2 * c2) * 224 + 2 * pb + 4];
            b0.f = *(const float4*)&hsk[(2 * c2 + 1) * 224 + 2 * pb];
            b1.f = *(const float4*)&hsk[(2 * c2 + 1) * 224 + 2 * pb + 4];
            unsigned long long hA[4] = {a0.u[0], a0.u[1], a1.u[0], a1.u[1]};
            unsigned long long hB[4] = {b0.u[0], b0.u[1], b1.u[0], b1.u[1]};

            #pragma unroll
            for (int i = 0; i < 7; i++) {
                float wl, wh;
                unpk2(w2[i], wl, wh);
                unsigned long long wll = pk2f(wl, wl);
                unsigned long long whh = pk2f(wh, wh);
                #pragma unroll
                for (int j = 0; j < 4; j++) kacc[i][j] = ffma2(wll, hA[j], kacc[i][j]);
                #pragma unroll
                for (int j = 0; j < 4; j++) kacc[i][j] = ffma2(whh, hB[j], kacc[i][j]);
            }
        }
    }
    __syncthreads();   // all hs reads complete before kern overwrite

    if (p1act) {
        #pragma unroll
        for (int i = 0; i < 7; i++) {
            float bias = sbias[kkg * 7 + i];
            unsigned long long bd = pk2f(bias, bias);
            F4 s0, s1;
            s0.u[0] = add2(kacc[i][0], bd);
            s0.u[1] = add2(kacc[i][1], bd);
            s1.u[0] = add2(kacc[i][2], bd);
            s1.u[1] = add2(kacc[i][3], bd);
            *(float4*)&hsk[(kkg * 7 + i) * KSTR + 2 * pb]     = s0.f;
            *(float4*)&hsk[(kkg * 7 + i) * KSTR + 2 * pb + 4] = s1.f;
        }
    }
    __syncthreads();

    // ---- Phase 2: apply. thread = 4 px x 4 interleaved channels ----
    if (tid < 224) {
        const int pd  = tid >> 2;          // 0..55
        const int cq  = tid & 3;
        const int lr  = pd / 14;
        const int pc4 = pd - lr * 14;
        const int pix0 = 4 * pd;           // = lr*56 + 4*pc4
        const int col0 = 4 * pc4;
        const int row  = r0 + lr;

        unsigned long long acc[4][2];
        #pragma unroll
        for (int i = 0; i < 4; i++)
            #pragma unroll
            for (int j = 0; j < 2; j++) acc[i][j] = 0ull;

        #pragma unroll 1
        for (int kh = 0; kh < 7; kh++) {
            unsigned long long kc2[7][2];
            #pragma unroll
            for (int kw = 0; kw < 7; kw++)
                #pragma unroll
                for (int j = 0; j < 2; j++) {
                    F2 t; t.f = *(const float2*)&hsk[(kh * 7 + kw) * KSTR + pix0 + 2 * j];
                    kc2[kw][j] = t.u;
                }

            #pragma unroll
            for (int i = 0; i < 4; i++) {
                const int ch = cq + 4 * i;           // interleaved channels
                const float* xr = &xt[ch * XCH + (lr + kh) * 62 + col0];
                F2 P[5];
                #pragma unroll
                for (int s = 0; s < 5; s++) P[s].f = *(const float2*)&xr[2 * s];
                unsigned long long M[4];
                #pragma unroll
                for (int s = 0; s < 4; s++) M[s] = pk2f(P[s].f.y, P[s + 1].f.x);

                acc[i][0] = ffma2(kc2[0][0], P[0].u, acc[i][0]);
                acc[i][0] = ffma2(kc2[1][0], M[0],   acc[i][0]);
                acc[i][0] = ffma2(kc2[2][0], P[1].u, acc[i][0]);
                acc[i][0] = ffma2(kc2[3][0], M[1],   acc[i][0]);
                acc[i][0] = ffma2(kc2[4][0], P[2].u, acc[i][0]);
                acc[i][0] = ffma2(kc2[5][0], M[2],   acc[i][0]);
                acc[i][0] = ffma2(kc2[6][0], P[3].u, acc[i][0]);

                acc[i][1] = ffma2(kc2[0][1], P[1].u, acc[i][1]);
                acc[i][1] = ffma2(kc2[1][1], M[1],   acc[i][1]);
                acc[i][1] = ffma2(kc2[2][1], P[2].u, acc[i][1]);
                acc[i][1] = ffma2(kc2[3][1], M[2],   acc[i][1]);
                acc[i][1] = ffma2(kc2[4][1], P[3].u, acc[i][1]);
                acc[i][1] = ffma2(kc2[5][1], M[3],   acc[i][1]);
                acc[i][1] = ffma2(kc2[6][1], P[4].u, acc[i][1]);
            }
        }

        #pragma unroll
        for (int i = 0; i < 4; i++) {
            const int ch = cq + 4 * i;
            #pragma unroll
            for (int j = 0; j < 2; j++) {
                F2 r; r.u = acc[i][j];
                *(float2*)&out[(b * 256 + g * 16 + ch) * HW + row * 56 + col0 + 2 * j] = r.f;
            }
        }
    }
}

extern "C" void kernel_launch(void* const* d_in, const int* in_sizes, int n_in,
                              void* d_out, int out_size)
{
    const float* x  = (const float*)d_in[0];
    const float* rw = (const float*)d_in[1];
    const float* rb = (const float*)d_in[2];
    const float* sw = (const float*)d_in[3];
    const float* sb = (const float*)d_in[4];
    float* out = (float*)d_out;

    const int smem2 = (3240 + 72 + 14336 + 16 * XCH) * sizeof(float); // ~111 KB
    cudaFuncSetAttribute(inv_kernel, cudaFuncAttributeMaxDynamicSharedMemorySize, smem2);

    reduce_kernel<<<dim3(28, 4), 256>>>(x, rw, rb);
    inv_kernel<<<dim3(14, 16, 4), 256, smem2>>>(x, sw, sb, out);
}